// round 1
// baseline (speedup 1.0000x reference)
#include <cuda_runtime.h>

// Problem constants
// B=256, T=256, C=384, H=6, hd=64, 3C=1152
#define BATCH 256
#define SEQ   256
#define CDIM  384
#define NH    6
#define HD    64
#define C3    1152
#define MTOT  (BATCH * SEQ)      // 65536

// Scratch (device globals -- allocation-guard safe)
__device__ float g_qkv[(size_t)MTOT * C3];   // 302 MB
__device__ float g_att[(size_t)MTOT * CDIM]; // 100 MB

// ---------------- f32x2 packed-FMA helpers (sm_100+) ----------------
typedef unsigned long long u64;

__device__ __forceinline__ u64 pk2(float lo, float hi) {
    u64 r;
    asm("mov.b64 %0, {%1, %2};" : "=l"(r) : "f"(lo), "f"(hi));
    return r;
}
__device__ __forceinline__ void fma2(u64& c, u64 a, u64 b) {
    asm("fma.rn.f32x2 %0, %1, %2, %0;" : "+l"(c) : "l"(a), "l"(b));
}
__device__ __forceinline__ float2 upk(u64 v) {
    float2 f;
    asm("mov.b64 {%0, %1}, %2;" : "=f"(f.x), "=f"(f.y) : "l"(v));
    return f;
}

// ---------------- Tiled GEMM: C[M,N] = A[M,K] @ B[K,N] (+bias) ----------------
// BM=BN=128, BK=16, 256 threads, 8x8 per thread via f32x2 (acc = 8 rows x 4 col-pairs).
template <int WITH_BIAS>
__global__ __launch_bounds__(256, 2)
void gemm_kernel(const float* __restrict__ A, const float* __restrict__ Bm,
                 const float* __restrict__ bias, float* __restrict__ C,
                 int M, int N, int K)
{
    __shared__ float As[16][128];   // transposed A tile: As[k][m]
    __shared__ float Bs[16][128];   // Bs[k][n]

    const int tid = threadIdx.x;
    const int m0 = blockIdx.y * 128;
    const int n0 = blockIdx.x * 128;

    const int aRow = tid >> 2;          // 0..63
    const int aCol = (tid & 3) << 2;    // 0,4,8,12
    const int bRow = tid >> 5;          // 0..7
    const int bCol = (tid & 31) << 2;   // 0..124

    const int ty = tid >> 4;            // 0..15
    const int tx = tid & 15;            // 0..15

    u64 acc[8][4];
#pragma unroll
    for (int i = 0; i < 8; i++)
#pragma unroll
        for (int j = 0; j < 4; j++) acc[i][j] = 0ULL;

    for (int k0 = 0; k0 < K; k0 += 16) {
#pragma unroll
        for (int p = 0; p < 2; p++) {
            float4 av = *(const float4*)(A + (long)(m0 + aRow + p * 64) * K + k0 + aCol);
            As[aCol + 0][aRow + p * 64] = av.x;
            As[aCol + 1][aRow + p * 64] = av.y;
            As[aCol + 2][aRow + p * 64] = av.z;
            As[aCol + 3][aRow + p * 64] = av.w;
            float4 bv = *(const float4*)(Bm + (long)(k0 + bRow + p * 8) * N + n0 + bCol);
            *(float4*)(&Bs[bRow + p * 8][bCol]) = bv;
        }
        __syncthreads();
#pragma unroll
        for (int kk = 0; kk < 16; kk++) {
            float4 a0 = *(const float4*)(&As[kk][ty * 4]);
            float4 a1 = *(const float4*)(&As[kk][64 + ty * 4]);
            float4 b0 = *(const float4*)(&Bs[kk][tx * 4]);
            float4 b1 = *(const float4*)(&Bs[kk][64 + tx * 4]);
            u64 bp[4];
            bp[0] = pk2(b0.x, b0.y);
            bp[1] = pk2(b0.z, b0.w);
            bp[2] = pk2(b1.x, b1.y);
            bp[3] = pk2(b1.z, b1.w);
            float a[8] = {a0.x, a0.y, a0.z, a0.w, a1.x, a1.y, a1.z, a1.w};
#pragma unroll
            for (int i = 0; i < 8; i++) {
                u64 ap = pk2(a[i], a[i]);
#pragma unroll
                for (int j = 0; j < 4; j++) fma2(acc[i][j], ap, bp[j]);
            }
        }
        __syncthreads();
    }

    // Epilogue: rows = m0 + {ty*4+i (i<4), 64+ty*4+i-4}, col groups = n0+tx*4 and n0+64+tx*4
#pragma unroll
    for (int i = 0; i < 8; i++) {
        int m = m0 + ((i < 4) ? (ty * 4 + i) : (64 + ty * 4 + i - 4));
#pragma unroll
        for (int jh = 0; jh < 2; jh++) {
            int n = n0 + ((jh == 0) ? (tx * 4) : (64 + tx * 4));
            float2 v0 = upk(acc[i][jh * 2 + 0]);
            float2 v1 = upk(acc[i][jh * 2 + 1]);
            float4 o = make_float4(v0.x, v0.y, v1.x, v1.y);
            if (WITH_BIAS) {
                o.x += bias[n + 0];
                o.y += bias[n + 1];
                o.z += bias[n + 2];
                o.w += bias[n + 3];
            }
            *(float4*)(C + (long)m * N + n) = o;
        }
    }
}

// ---------------- Fused attention per (b, h, 64-query block) ----------------
// smem: Qs[64][65], Ks[256][65], Vs[256][64], Sm[64][264]  -> 216,320 B dynamic
#define QS_STRIDE 65
#define KS_STRIDE 65
#define VS_STRIDE 64
#define SM_STRIDE 264
#define ATTN_SMEM_BYTES ((64 * QS_STRIDE + 256 * KS_STRIDE + 256 * VS_STRIDE + 64 * SM_STRIDE) * 4)

__global__ __launch_bounds__(256, 1)
void attn_kernel(const float* __restrict__ qkv, float* __restrict__ att)
{
    extern __shared__ float sm[];
    float* Qs = sm;                        // 64*65
    float* Ks = Qs + 64 * QS_STRIDE;       // 256*65
    float* Vs = Ks + 256 * KS_STRIDE;      // 256*64
    float* Sm = Vs + 256 * VS_STRIDE;      // 64*264

    const int tid = threadIdx.x;
    const int blk = blockIdx.x;
    const int qb = blk & 3;                 // query block (4 x 64 rows)
    const int h  = (blk >> 2) % NH;
    const int b  = blk / (NH * 4);
    const float* qkvb = qkv + (long)b * SEQ * C3;

    // ---- Stage Q (64x64), K (256x64), V (256x64) ----
#pragma unroll
    for (int p = 0; p < 4; p++) {           // Q: 1024 float4
        int idx = tid + p * 256;
        int r = idx >> 4, f4 = idx & 15;
        float4 v = *(const float4*)(qkvb + (long)(qb * 64 + r) * C3 + h * HD + f4 * 4);
        float* dst = Qs + r * QS_STRIDE + f4 * 4;
        dst[0] = v.x; dst[1] = v.y; dst[2] = v.z; dst[3] = v.w;
    }
#pragma unroll
    for (int p = 0; p < 16; p++) {          // K: 4096 float4
        int idx = tid + p * 256;
        int r = idx >> 4, f4 = idx & 15;
        float4 v = *(const float4*)(qkvb + (long)r * C3 + CDIM + h * HD + f4 * 4);
        float* dst = Ks + r * KS_STRIDE + f4 * 4;
        dst[0] = v.x; dst[1] = v.y; dst[2] = v.z; dst[3] = v.w;
    }
#pragma unroll
    for (int p = 0; p < 16; p++) {          // V: 4096 float4 (keep row-major, aligned)
        int idx = tid + p * 256;
        int r = idx >> 4, f4 = idx & 15;
        float4 v = *(const float4*)(qkvb + (long)r * C3 + 2 * CDIM + h * HD + f4 * 4);
        *(float4*)(Vs + r * VS_STRIDE + f4 * 4) = v;
    }
    __syncthreads();

    // ---- S = Q @ K^T  (64 x 256), warp-row layout ----
    // ty = warp id (0..7): rows ty*8..ty*8+7 ; tx = lane (0..31): cols tx*8..tx*8+7
    const int ty = tid >> 5;
    const int tx = tid & 31;

    u64 acc[8][4];
#pragma unroll
    for (int i = 0; i < 8; i++)
#pragma unroll
        for (int j = 0; j < 4; j++) acc[i][j] = 0ULL;

#pragma unroll 8
    for (int kk = 0; kk < HD; kk++) {
        float a[8];
        u64 bp[4];
#pragma unroll
        for (int i = 0; i < 8; i++) a[i] = Qs[(ty * 8 + i) * QS_STRIDE + kk];
#pragma unroll
        for (int j = 0; j < 4; j++) {
            float blo = Ks[(tx * 8 + 2 * j + 0) * KS_STRIDE + kk];
            float bhi = Ks[(tx * 8 + 2 * j + 1) * KS_STRIDE + kk];
            bp[j] = pk2(blo, bhi);
        }
#pragma unroll
        for (int i = 0; i < 8; i++) {
            u64 ap = pk2(a[i], a[i]);
#pragma unroll
            for (int j = 0; j < 4; j++) fma2(acc[i][j], ap, bp[j]);
        }
    }

    // ---- Causal mask + softmax per row (all in registers + warp shuffles) ----
#pragma unroll
    for (int i = 0; i < 8; i++) {
        const int rg = qb * 64 + ty * 8 + i;   // global query index in [0,255]
        float s[8];
        float2 v;
        v = upk(acc[i][0]); s[0] = v.x; s[1] = v.y;
        v = upk(acc[i][1]); s[2] = v.x; s[3] = v.y;
        v = upk(acc[i][2]); s[4] = v.x; s[5] = v.y;
        v = upk(acc[i][3]); s[6] = v.x; s[7] = v.y;

        float m = -1e30f;
#pragma unroll
        for (int j = 0; j < 8; j++) {
            if (tx * 8 + j > rg) s[j] = -1e30f;
            m = fmaxf(m, s[j]);
        }
#pragma unroll
        for (int o = 16; o > 0; o >>= 1) m = fmaxf(m, __shfl_xor_sync(0xffffffffu, m, o));

        float p[8];
        float sum = 0.0f;
#pragma unroll
        for (int j = 0; j < 8; j++) {
            float e = (tx * 8 + j > rg) ? 0.0f : __expf(s[j] - m);
            p[j] = e;
            sum += e;
        }
#pragma unroll
        for (int o = 16; o > 0; o >>= 1) sum += __shfl_xor_sync(0xffffffffu, sum, o);
        float inv = 1.0f / sum;

        float* dst = Sm + (ty * 8 + i) * SM_STRIDE + tx * 8;
        *(float4*)(dst + 0) = make_float4(p[0] * inv, p[1] * inv, p[2] * inv, p[3] * inv);
        *(float4*)(dst + 4) = make_float4(p[4] * inv, p[5] * inv, p[6] * inv, p[7] * inv);
    }
    __syncthreads();

    // ---- O = P @ V  (64 x 64) ----
    // ty2 = tid/16 (0..15): rows ty2*4..+3 ; tx2 = tid%16: cols tx2*4..+3
    const int ty2 = tid >> 4;
    const int tx2 = tid & 15;

    u64 oacc[4][2];
#pragma unroll
    for (int i = 0; i < 4; i++) { oacc[i][0] = 0ULL; oacc[i][1] = 0ULL; }

#pragma unroll 4
    for (int kk = 0; kk < 256; kk++) {
        float4 bv = *(const float4*)(Vs + kk * VS_STRIDE + tx2 * 4);
        u64 bp0 = pk2(bv.x, bv.y);
        u64 bp1 = pk2(bv.z, bv.w);
#pragma unroll
        for (int i = 0; i < 4; i++) {
            float av = Sm[(ty2 * 4 + i) * SM_STRIDE + kk];
            u64 ap = pk2(av, av);
            fma2(oacc[i][0], ap, bp0);
            fma2(oacc[i][1], ap, bp1);
        }
    }

#pragma unroll
    for (int i = 0; i < 4; i++) {
        int t = qb * 64 + ty2 * 4 + i;
        float2 x0 = upk(oacc[i][0]);
        float2 x1 = upk(oacc[i][1]);
        *(float4*)(att + ((long)(b * SEQ + t)) * CDIM + h * HD + tx2 * 4) =
            make_float4(x0.x, x0.y, x1.x, x1.y);
    }
}

// ---------------- launch ----------------
extern "C" void kernel_launch(void* const* d_in, const int* in_sizes, int n_in,
                              void* d_out, int out_size)
{
    const float* x     = (const float*)d_in[0];
    const float* Wqkv  = (const float*)d_in[1];
    const float* Wproj = (const float*)d_in[2];
    const float* bproj = (const float*)d_in[3];
    float* out = (float*)d_out;

    float* qkvp = nullptr;
    float* attp = nullptr;
    cudaGetSymbolAddress((void**)&qkvp, g_qkv);
    cudaGetSymbolAddress((void**)&attp, g_att);

    cudaFuncSetAttribute(attn_kernel, cudaFuncAttributeMaxDynamicSharedMemorySize,
                         ATTN_SMEM_BYTES);

    // 1) qkv = x @ Wqkv            [65536 x 1152], K=384
    gemm_kernel<0><<<dim3(C3 / 128, MTOT / 128), 256>>>(x, Wqkv, nullptr, qkvp,
                                                        MTOT, C3, CDIM);
    // 2) fused causal attention    grid = B * H * 4 query-blocks
    attn_kernel<<<BATCH * NH * 4, 256, ATTN_SMEM_BYTES>>>(qkvp, attp);
    // 3) out = att @ Wproj + bias  [65536 x 384], K=384
    gemm_kernel<1><<<dim3(CDIM / 128, MTOT / 128), 256>>>(attp, Wproj, bproj, out,
                                                          MTOT, CDIM, CDIM);
}

// round 9
// speedup vs baseline: 1.7507x; 1.7507x over previous
#include <cuda_runtime.h>
#include <cuda_bf16.h>
#include <cstdint>

// B=256, T=256, C=384, H=6, hd=64
#define BATCH 256
#define SEQ   256
#define CDIM  384
#define NH    6
#define HD    64
#define C3    1152
#define MTOT  65536

// ---------------- scratch (device globals; allocation-guard safe) -------------
__device__ float          mha_qkv[(size_t)MTOT * C3];     // fp32 qkv for attention
__device__ __nv_bfloat16  mha_xh[(size_t)MTOT * CDIM];
__device__ __nv_bfloat16  mha_xl[(size_t)MTOT * CDIM];
__device__ __nv_bfloat16  mha_ath[(size_t)MTOT * CDIM];
__device__ __nv_bfloat16  mha_atl[(size_t)MTOT * CDIM];
__device__ __nv_bfloat16  mha_wqh[(size_t)C3 * CDIM];     // Wqkv^T [N=1152][K=384]
__device__ __nv_bfloat16  mha_wql[(size_t)C3 * CDIM];
__device__ __nv_bfloat16  mha_wph[(size_t)CDIM * CDIM];   // Wproj^T [384][384]
__device__ __nv_bfloat16  mha_wpl[(size_t)CDIM * CDIM];

// ---------------- f32x2 packed-FMA helpers ----------------
typedef unsigned long long u64;
__device__ __forceinline__ u64 pk2(float lo, float hi) {
    u64 r; asm("mov.b64 %0, {%1, %2};" : "=l"(r) : "f"(lo), "f"(hi)); return r;
}
__device__ __forceinline__ void fma2(u64& c, u64 a, u64 b) {
    asm("fma.rn.f32x2 %0, %1, %2, %0;" : "+l"(c) : "l"(a), "l"(b));
}
__device__ __forceinline__ float2 upk(u64 v) {
    float2 f; asm("mov.b64 {%0, %1}, %2;" : "=f"(f.x), "=f"(f.y) : "l"(v)); return f;
}

// ---------------- mma.sync / ldmatrix / cp.async helpers (sm_80 base) ---------
__device__ __forceinline__ uint32_t smem_u32(const void* p) {
    uint32_t a;
    asm("{ .reg .u64 t; cvta.to.shared.u64 t, %1; cvt.u32.u64 %0, t; }" : "=r"(a) : "l"(p));
    return a;
}
__device__ __forceinline__ void ldsm4(uint32_t* r, uint32_t a) {
    asm volatile("ldmatrix.sync.aligned.m8n8.x4.shared.b16 {%0,%1,%2,%3}, [%4];"
                 : "=r"(r[0]), "=r"(r[1]), "=r"(r[2]), "=r"(r[3]) : "r"(a));
}
__device__ __forceinline__ void ldsm2(uint32_t* r, uint32_t a) {
    asm volatile("ldmatrix.sync.aligned.m8n8.x2.shared.b16 {%0,%1}, [%2];"
                 : "=r"(r[0]), "=r"(r[1]) : "r"(a));
}
__device__ __forceinline__ void mma_bf16(float* d, const uint32_t* a, const uint32_t* b) {
    asm volatile("mma.sync.aligned.m16n8k16.row.col.f32.bf16.bf16.f32 "
                 "{%0,%1,%2,%3}, {%4,%5,%6,%7}, {%8,%9}, {%0,%1,%2,%3};"
                 : "+f"(d[0]), "+f"(d[1]), "+f"(d[2]), "+f"(d[3])
                 : "r"(a[0]), "r"(a[1]), "r"(a[2]), "r"(a[3]), "r"(b[0]), "r"(b[1]));
}
#define CP16(dst, src) \
    asm volatile("cp.async.cg.shared.global [%0], [%1], 16;" :: "r"(dst), "l"(src) : "memory")
#define CP_COMMIT() asm volatile("cp.async.commit_group;" ::: "memory")
#define CP_WAIT0()  asm volatile("cp.async.wait_group 0;" ::: "memory")

// ---------------- bf16 hi/lo split kernels ----------------
__global__ void split_kernel(const float* __restrict__ in, __nv_bfloat16* __restrict__ h,
                             __nv_bfloat16* __restrict__ l, int n4)
{
    int i = blockIdx.x * blockDim.x + threadIdx.x;
    if (i >= n4) return;
    float4 v = ((const float4*)in)[i];
    __nv_bfloat16 h0 = __float2bfloat16_rn(v.x), h1 = __float2bfloat16_rn(v.y);
    __nv_bfloat16 h2 = __float2bfloat16_rn(v.z), h3 = __float2bfloat16_rn(v.w);
    __nv_bfloat16 l0 = __float2bfloat16_rn(v.x - __bfloat162float(h0));
    __nv_bfloat16 l1 = __float2bfloat16_rn(v.y - __bfloat162float(h1));
    __nv_bfloat16 l2 = __float2bfloat16_rn(v.z - __bfloat162float(h2));
    __nv_bfloat16 l3 = __float2bfloat16_rn(v.w - __bfloat162float(h3));
    __nv_bfloat162 a, b;
    a.x = h0; a.y = h1; b.x = h2; b.y = h3;
    ((__nv_bfloat162*)h)[2 * i] = a; ((__nv_bfloat162*)h)[2 * i + 1] = b;
    a.x = l0; a.y = l1; b.x = l2; b.y = l3;
    ((__nv_bfloat162*)l)[2 * i] = a; ((__nv_bfloat162*)l)[2 * i + 1] = b;
}

// transpose W[K][N] -> Wt[N][K] with hi/lo split
__global__ void split_t_kernel(const float* __restrict__ W, __nv_bfloat16* __restrict__ th,
                               __nv_bfloat16* __restrict__ tl, int K, int N)
{
    int idx = blockIdx.x * blockDim.x + threadIdx.x;
    if (idx >= K * N) return;
    int k = idx / N, n = idx % N;
    float v = W[idx];
    __nv_bfloat16 hb = __float2bfloat16_rn(v);
    __nv_bfloat16 lb = __float2bfloat16_rn(v - __bfloat162float(hb));
    th[(size_t)n * K + k] = hb;
    tl[(size_t)n * K + k] = lb;
}

// ---------------- mma.sync GEMM: C[M,N] = (Ah+Al)[M,K] @ (Bh+Bl)^T[N,K] -------
// CTA 128x128, K-chunk 32, double-buffered cp.async. 8 warps, warp tile 64x32.
// smem per buffer: Ah,Al,Bh,Bl tiles of 128 rows x 32 bf16, row stride 80B
// (stride 80B => ldmatrix 8-row phases hit 8 distinct 16B groups: conflict-free).
#define TSTRIDE 80
#define TILE_B  (128 * TSTRIDE)          // 10240 B per tile
#define BUF_B   (4 * TILE_B)             // 40960 B per buffer
#define GEMM_SMEM (2 * BUF_B)            // 81920 B

template <int WITH_BIAS>
__global__ void __launch_bounds__(256, 1)
mma_gemm(const __nv_bfloat16* __restrict__ Ah, const __nv_bfloat16* __restrict__ Al,
         const __nv_bfloat16* __restrict__ Bh, const __nv_bfloat16* __restrict__ Bl,
         const float* __restrict__ bias, float* __restrict__ C, int M, int N, int K)
{
    extern __shared__ char smem[];
    const uint32_t sb = smem_u32(smem);
    const int tid = threadIdx.x;
    const int wid = tid >> 5;
    const int lane = tid & 31;
    const int m0 = blockIdx.y * 128;
    const int n0 = blockIdx.x * 128;
    const int wm0 = (wid & 1) * 64;      // warp M offset within CTA tile
    const int wn0 = (wid >> 1) * 32;     // warp N offset

    float acc[4][4][4];
#pragma unroll
    for (int i = 0; i < 4; i++)
#pragma unroll
        for (int j = 0; j < 4; j++)
#pragma unroll
            for (int q = 0; q < 4; q++) acc[i][j][q] = 0.0f;

    const int NC = K / 32;

    auto load_chunk = [&](int c, int buf) {
        const int k0 = c * 32;
        const uint32_t bo = sb + buf * BUF_B;
#pragma unroll
        for (int t = 0; t < 2; t++) {
            int s = tid + t * 256;           // 0..511
            int row = s >> 2, c16 = s & 3;   // 128 rows x 4 16B segs
            uint32_t d = bo + row * TSTRIDE + c16 * 16;
            const __nv_bfloat16* sa = Ah + (size_t)(m0 + row) * K + k0 + c16 * 8;
            CP16(d, sa);
            const __nv_bfloat16* sal = Al + (size_t)(m0 + row) * K + k0 + c16 * 8;
            CP16(d + TILE_B, sal);
            const __nv_bfloat16* sbh = Bh + (size_t)(n0 + row) * K + k0 + c16 * 8;
            CP16(d + 2 * TILE_B, sbh);
            const __nv_bfloat16* sbl = Bl + (size_t)(n0 + row) * K + k0 + c16 * 8;
            CP16(d + 3 * TILE_B, sbl);
        }
        CP_COMMIT();
    };

    load_chunk(0, 0);

    for (int c = 0; c < NC; c++) {
        CP_WAIT0();
        __syncthreads();                 // chunk c visible to all warps
        if (c + 1 < NC) load_chunk(c + 1, (c + 1) & 1);

        const uint32_t bo = sb + (c & 1) * BUF_B;
        const int l4 = lane & 15;
#pragma unroll
        for (int ks = 0; ks < 2; ks++) {
            uint32_t ah[4][4], al[4][4], bh[4][2], bl[4][2];
            const uint32_t colA = ks * 32 + (lane >> 4) * 16;
            const uint32_t colB = ks * 32 + (l4 >> 3) * 16;
#pragma unroll
            for (int i = 0; i < 4; i++) {
                uint32_t a = bo + (uint32_t)(wm0 + i * 16 + l4) * TSTRIDE + colA;
                ldsm4(ah[i], a);
                ldsm4(al[i], a + TILE_B);
            }
#pragma unroll
            for (int j = 0; j < 4; j++) {
                uint32_t a = bo + 2 * TILE_B + (uint32_t)(wn0 + j * 8 + (l4 & 7)) * TSTRIDE + colB;
                ldsm2(bh[j], a);
                ldsm2(bl[j], a + TILE_B);
            }
#pragma unroll
            for (int i = 0; i < 4; i++)
#pragma unroll
                for (int j = 0; j < 4; j++) {
                    mma_bf16(acc[i][j], ah[i], bh[j]);
                    mma_bf16(acc[i][j], ah[i], bl[j]);
                    mma_bf16(acc[i][j], al[i], bh[j]);
                }
        }
        __syncthreads();                 // buffer c&1 free for chunk c+2
    }

    // ---- epilogue: direct stores (float2 per fragment half) ----
#pragma unroll
    for (int i = 0; i < 4; i++) {
#pragma unroll
        for (int j = 0; j < 4; j++) {
            int m = m0 + wm0 + i * 16 + (lane >> 2);
            int n = n0 + wn0 + j * 8 + (lane & 3) * 2;
            float2 v0 = make_float2(acc[i][j][0], acc[i][j][1]);
            float2 v1 = make_float2(acc[i][j][2], acc[i][j][3]);
            if (WITH_BIAS) {
                float2 bv = *(const float2*)(bias + n);
                v0.x += bv.x; v0.y += bv.y;
                v1.x += bv.x; v1.y += bv.y;
            }
            *(float2*)(C + (size_t)m * N + n) = v0;
            *(float2*)(C + (size_t)(m + 8) * N + n) = v1;
        }
    }
}

// ---------------- Fused causal attention, templated on query block ----------------
// QB in 0..3; kv_len = (QB+1)*64. Writes bf16 hi/lo att directly.
template <int QB>
__global__ void __launch_bounds__(256)
attn_kernel(const float* __restrict__ qkv, __nv_bfloat16* __restrict__ ath,
            __nv_bfloat16* __restrict__ atl)
{
    constexpr int KVLEN = (QB + 1) * 64;
    constexpr int JMAX = QB + 1;
    constexpr int QS = 65, KS = 65, VS = 64, SMS = KVLEN + 1;

    extern __shared__ float sm[];
    float* Qs = sm;                    // 64 x 65
    float* Ks = Qs + 64 * QS;          // KVLEN x 65
    float* Vs = Ks + KVLEN * KS;       // KVLEN x 64
    float* Sm = Vs + KVLEN * VS;       // 64 x SMS

    const int tid = threadIdx.x;
    const int blk = blockIdx.x;
    const int hh = blk % NH;
    const int b = blk / NH;
    const float* qkvb = qkv + (size_t)b * SEQ * C3;

    // ---- stage Q (64x64) ----
#pragma unroll
    for (int p = 0; p < 4; p++) {
        int idx = tid + p * 256;
        int r = idx >> 4, f4 = idx & 15;
        float4 v = *(const float4*)(qkvb + (size_t)(QB * 64 + r) * C3 + hh * HD + f4 * 4);
        float* dst = Qs + r * QS + f4 * 4;
        dst[0] = v.x; dst[1] = v.y; dst[2] = v.z; dst[3] = v.w;
    }
    // ---- stage K (KVLEN x 64) ----
#pragma unroll
    for (int p = 0; p < JMAX * 4; p++) {
        int idx = tid + p * 256;
        int r = idx >> 4, f4 = idx & 15;
        float4 v = *(const float4*)(qkvb + (size_t)r * C3 + CDIM + hh * HD + f4 * 4);
        float* dst = Ks + r * KS + f4 * 4;
        dst[0] = v.x; dst[1] = v.y; dst[2] = v.z; dst[3] = v.w;
    }
    // ---- stage V (KVLEN x 64) ----
#pragma unroll
    for (int p = 0; p < JMAX * 4; p++) {
        int idx = tid + p * 256;
        int r = idx >> 4, f4 = idx & 15;
        float4 v = *(const float4*)(qkvb + (size_t)r * C3 + 2 * CDIM + hh * HD + f4 * 4);
        *(float4*)(Vs + r * VS + f4 * 4) = v;
    }
    __syncthreads();

    // ---- S = Q @ K^T, rows per warp, strided cols per lane ----
    const int ty = tid >> 5;
    const int tx = tid & 31;

    u64 acc[8][JMAX];
#pragma unroll
    for (int i = 0; i < 8; i++)
#pragma unroll
        for (int j = 0; j < JMAX; j++) acc[i][j] = 0ULL;

#pragma unroll 8
    for (int kk = 0; kk < HD; kk++) {
        float a[8];
        u64 bp[JMAX];
#pragma unroll
        for (int i = 0; i < 8; i++) a[i] = Qs[(ty * 8 + i) * QS + kk];
#pragma unroll
        for (int j = 0; j < JMAX; j++)
            bp[j] = pk2(Ks[(tx + 64 * j) * KS + kk], Ks[(tx + 64 * j + 32) * KS + kk]);
#pragma unroll
        for (int i = 0; i < 8; i++) {
            u64 ap = pk2(a[i], a[i]);
#pragma unroll
            for (int j = 0; j < JMAX; j++) fma2(acc[i][j], ap, bp[j]);
        }
    }

    // ---- causal mask + softmax (registers + shuffles) ----
#pragma unroll
    for (int i = 0; i < 8; i++) {
        const int rg = QB * 64 + ty * 8 + i;
        float s[2 * JMAX];
#pragma unroll
        for (int j = 0; j < JMAX; j++) {
            float2 v = upk(acc[i][j]);
            s[2 * j] = (tx + 64 * j > rg) ? -1e30f : v.x;
            s[2 * j + 1] = (tx + 64 * j + 32 > rg) ? -1e30f : v.y;
        }
        float m = -1e30f;
#pragma unroll
        for (int j = 0; j < 2 * JMAX; j++) m = fmaxf(m, s[j]);
#pragma unroll
        for (int o = 16; o > 0; o >>= 1) m = fmaxf(m, __shfl_xor_sync(0xffffffffu, m, o));

        float p[2 * JMAX];
        float sum = 0.0f;
#pragma unroll
        for (int j = 0; j < 2 * JMAX; j++) {
            float e = (s[j] <= -1e29f) ? 0.0f : __expf(s[j] - m);
            p[j] = e; sum += e;
        }
#pragma unroll
        for (int o = 16; o > 0; o >>= 1) sum += __shfl_xor_sync(0xffffffffu, sum, o);
        float inv = 1.0f / sum;

        float* row = Sm + (ty * 8 + i) * SMS;
#pragma unroll
        for (int j = 0; j < JMAX; j++) {
            row[tx + 64 * j] = p[2 * j] * inv;
            row[tx + 64 * j + 32] = p[2 * j + 1] * inv;
        }
    }
    __syncthreads();

    // ---- O = P @ V ----
    const int ty2 = tid >> 4;   // rows ty2*4..+3
    const int tx2 = tid & 15;   // cols tx2*4..+3

    u64 oacc[4][2];
#pragma unroll
    for (int i = 0; i < 4; i++) { oacc[i][0] = 0ULL; oacc[i][1] = 0ULL; }

#pragma unroll 4
    for (int kk = 0; kk < KVLEN; kk++) {
        float4 bv = *(const float4*)(Vs + kk * VS + tx2 * 4);
        u64 bp0 = pk2(bv.x, bv.y);
        u64 bp1 = pk2(bv.z, bv.w);
#pragma unroll
        for (int i = 0; i < 4; i++) {
            float av = Sm[(ty2 * 4 + i) * SMS + kk];
            u64 ap = pk2(av, av);
            fma2(oacc[i][0], ap, bp0);
            fma2(oacc[i][1], ap, bp1);
        }
    }

#pragma unroll
    for (int i = 0; i < 4; i++) {
        int t = QB * 64 + ty2 * 4 + i;
        float2 x0 = upk(oacc[i][0]);
        float2 x1 = upk(oacc[i][1]);
        float o[4] = {x0.x, x0.y, x1.x, x1.y};
        size_t base = ((size_t)(b * SEQ + t)) * CDIM + hh * HD + tx2 * 4;
        __nv_bfloat16 hv[4], lv[4];
#pragma unroll
        for (int q = 0; q < 4; q++) {
            hv[q] = __float2bfloat16_rn(o[q]);
            lv[q] = __float2bfloat16_rn(o[q] - __bfloat162float(hv[q]));
        }
        __nv_bfloat162 t0, t1;
        t0.x = hv[0]; t0.y = hv[1]; t1.x = hv[2]; t1.y = hv[3];
        ((__nv_bfloat162*)(ath + base))[0] = t0;
        ((__nv_bfloat162*)(ath + base))[1] = t1;
        t0.x = lv[0]; t0.y = lv[1]; t1.x = lv[2]; t1.y = lv[3];
        ((__nv_bfloat162*)(atl + base))[0] = t0;
        ((__nv_bfloat162*)(atl + base))[1] = t1;
    }
}

// smem bytes per QB
template <int QB> struct AttnSmem {
    static constexpr int KVLEN = (QB + 1) * 64;
    static constexpr int BYTES = (64 * 65 + KVLEN * 65 + KVLEN * 64 + 64 * (KVLEN + 1)) * 4;
};

// ---------------- launch ----------------
extern "C" void kernel_launch(void* const* d_in, const int* in_sizes, int n_in,
                              void* d_out, int out_size)
{
    const float* x     = (const float*)d_in[0];
    const float* Wqkv  = (const float*)d_in[1];
    const float* Wproj = (const float*)d_in[2];
    const float* bproj = (const float*)d_in[3];
    float* out = (float*)d_out;

    float *qkvp = nullptr;
    __nv_bfloat16 *xh, *xl, *ath, *atl, *wqh, *wql, *wph, *wpl;
    cudaGetSymbolAddress((void**)&qkvp, mha_qkv);
    cudaGetSymbolAddress((void**)&xh, mha_xh);
    cudaGetSymbolAddress((void**)&xl, mha_xl);
    cudaGetSymbolAddress((void**)&ath, mha_ath);
    cudaGetSymbolAddress((void**)&atl, mha_atl);
    cudaGetSymbolAddress((void**)&wqh, mha_wqh);
    cudaGetSymbolAddress((void**)&wql, mha_wql);
    cudaGetSymbolAddress((void**)&wph, mha_wph);
    cudaGetSymbolAddress((void**)&wpl, mha_wpl);

    cudaFuncSetAttribute(mma_gemm<0>, cudaFuncAttributeMaxDynamicSharedMemorySize, GEMM_SMEM);
    cudaFuncSetAttribute(mma_gemm<1>, cudaFuncAttributeMaxDynamicSharedMemorySize, GEMM_SMEM);
    cudaFuncSetAttribute(attn_kernel<0>, cudaFuncAttributeMaxDynamicSharedMemorySize, AttnSmem<0>::BYTES);
    cudaFuncSetAttribute(attn_kernel<1>, cudaFuncAttributeMaxDynamicSharedMemorySize, AttnSmem<1>::BYTES);
    cudaFuncSetAttribute(attn_kernel<2>, cudaFuncAttributeMaxDynamicSharedMemorySize, AttnSmem<2>::BYTES);
    cudaFuncSetAttribute(attn_kernel<3>, cudaFuncAttributeMaxDynamicSharedMemorySize, AttnSmem<3>::BYTES);

    // 0) bf16 hi/lo splits
    {
        int n4 = MTOT * CDIM / 4;
        split_kernel<<<(n4 + 255) / 256, 256>>>(x, xh, xl, n4);
        int nw1 = CDIM * C3;
        split_t_kernel<<<(nw1 + 255) / 256, 256>>>(Wqkv, wqh, wql, CDIM, C3);
        int nw2 = CDIM * CDIM;
        split_t_kernel<<<(nw2 + 255) / 256, 256>>>(Wproj, wph, wpl, CDIM, CDIM);
    }

    // 1) qkv = x @ Wqkv  (mma.sync bf16x3, M=65536, N=1152, K=384)
    mma_gemm<0><<<dim3(C3 / 128, MTOT / 128), 256, GEMM_SMEM>>>(xh, xl, wqh, wql, nullptr,
                                                                qkvp, MTOT, C3, CDIM);

    // 2) fused causal attention (per query block template)
    attn_kernel<0><<<BATCH * NH, 256, AttnSmem<0>::BYTES>>>(qkvp, ath, atl);
    attn_kernel<1><<<BATCH * NH, 256, AttnSmem<1>::BYTES>>>(qkvp, ath, atl);
    attn_kernel<2><<<BATCH * NH, 256, AttnSmem<2>::BYTES>>>(qkvp, ath, atl);
    attn_kernel<3><<<BATCH * NH, 256, AttnSmem<3>::BYTES>>>(qkvp, ath, atl);

    // 3) out = att @ Wproj + bias  (mma.sync bf16x3, N=384, K=384)
    mma_gemm<1><<<dim3(CDIM / 128, MTOT / 128), 256, GEMM_SMEM>>>(ath, atl, wph, wpl, bproj,
                                                                  out, MTOT, CDIM, CDIM);
}

// round 16
// speedup vs baseline: 1.8995x; 1.0850x over previous
#include <cuda_runtime.h>
#include <cuda_bf16.h>
#include <cstdint>

// B=256, T=256, C=384, H=6, hd=64
#define BATCH 256
#define SEQ   256
#define CDIM  384
#define NH    6
#define HD    64
#define C3    1152
#define MTOT  65536

// ---------------- scratch (device globals; allocation-guard safe) -------------
__device__ float          mha_qkv[(size_t)MTOT * C3];     // fp32 qkv for attention
__device__ __nv_bfloat16  mha_xh[(size_t)MTOT * CDIM];
__device__ __nv_bfloat16  mha_xl[(size_t)MTOT * CDIM];
__device__ __nv_bfloat16  mha_ath[(size_t)MTOT * CDIM];
__device__ __nv_bfloat16  mha_atl[(size_t)MTOT * CDIM];
__device__ __nv_bfloat16  mha_wqh[(size_t)C3 * CDIM];     // Wqkv^T [N=1152][K=384]
__device__ __nv_bfloat16  mha_wql[(size_t)C3 * CDIM];
__device__ __nv_bfloat16  mha_wph[(size_t)CDIM * CDIM];   // Wproj^T [384][384]
__device__ __nv_bfloat16  mha_wpl[(size_t)CDIM * CDIM];

// ---------------- f32x2 packed-FMA helpers ----------------
typedef unsigned long long u64;
__device__ __forceinline__ u64 pk2(float lo, float hi) {
    u64 r; asm("mov.b64 %0, {%1, %2};" : "=l"(r) : "f"(lo), "f"(hi)); return r;
}
__device__ __forceinline__ void fma2(u64& c, u64 a, u64 b) {
    asm("fma.rn.f32x2 %0, %1, %2, %0;" : "+l"(c) : "l"(a), "l"(b));
}
__device__ __forceinline__ float2 upk(u64 v) {
    float2 f; asm("mov.b64 {%0, %1}, %2;" : "=f"(f.x), "=f"(f.y) : "l"(v)); return f;
}

// ---------------- mma.sync / ldmatrix / cp.async helpers (sm_80 base) ---------
__device__ __forceinline__ uint32_t smem_u32(const void* p) {
    uint32_t a;
    asm("{ .reg .u64 t; cvta.to.shared.u64 t, %1; cvt.u32.u64 %0, t; }" : "=r"(a) : "l"(p));
    return a;
}
__device__ __forceinline__ void ldsm4(uint32_t* r, uint32_t a) {
    asm volatile("ldmatrix.sync.aligned.m8n8.x4.shared.b16 {%0,%1,%2,%3}, [%4];"
                 : "=r"(r[0]), "=r"(r[1]), "=r"(r[2]), "=r"(r[3]) : "r"(a));
}
__device__ __forceinline__ void ldsm2(uint32_t* r, uint32_t a) {
    asm volatile("ldmatrix.sync.aligned.m8n8.x2.shared.b16 {%0,%1}, [%2];"
                 : "=r"(r[0]), "=r"(r[1]) : "r"(a));
}
__device__ __forceinline__ void mma_bf16(float* d, const uint32_t* a, const uint32_t* b) {
    asm volatile("mma.sync.aligned.m16n8k16.row.col.f32.bf16.bf16.f32 "
                 "{%0,%1,%2,%3}, {%4,%5,%6,%7}, {%8,%9}, {%0,%1,%2,%3};"
                 : "+f"(d[0]), "+f"(d[1]), "+f"(d[2]), "+f"(d[3])
                 : "r"(a[0]), "r"(a[1]), "r"(a[2]), "r"(a[3]), "r"(b[0]), "r"(b[1]));
}
#define CP16(dst, src) \
    asm volatile("cp.async.cg.shared.global [%0], [%1], 16;" :: "r"(dst), "l"(src) : "memory")
#define CP_COMMIT() asm volatile("cp.async.commit_group;" ::: "memory")
#define CP_WAIT0()  asm volatile("cp.async.wait_group 0;" ::: "memory")

// ---------------- bf16 hi/lo split kernels ----------------
__global__ void split_kernel(const float* __restrict__ in, __nv_bfloat16* __restrict__ h,
                             __nv_bfloat16* __restrict__ l, int n4)
{
    int i = blockIdx.x * blockDim.x + threadIdx.x;
    if (i >= n4) return;
    float4 v = ((const float4*)in)[i];
    __nv_bfloat16 h0 = __float2bfloat16_rn(v.x), h1 = __float2bfloat16_rn(v.y);
    __nv_bfloat16 h2 = __float2bfloat16_rn(v.z), h3 = __float2bfloat16_rn(v.w);
    __nv_bfloat16 l0 = __float2bfloat16_rn(v.x - __bfloat162float(h0));
    __nv_bfloat16 l1 = __float2bfloat16_rn(v.y - __bfloat162float(h1));
    __nv_bfloat16 l2 = __float2bfloat16_rn(v.z - __bfloat162float(h2));
    __nv_bfloat16 l3 = __float2bfloat16_rn(v.w - __bfloat162float(h3));
    __nv_bfloat162 a, b;
    a.x = h0; a.y = h1; b.x = h2; b.y = h3;
    ((__nv_bfloat162*)h)[2 * i] = a; ((__nv_bfloat162*)h)[2 * i + 1] = b;
    a.x = l0; a.y = l1; b.x = l2; b.y = l3;
    ((__nv_bfloat162*)l)[2 * i] = a; ((__nv_bfloat162*)l)[2 * i + 1] = b;
}

// transpose W[K][N] -> Wt[N][K] with hi/lo split
__global__ void split_t_kernel(const float* __restrict__ W, __nv_bfloat16* __restrict__ th,
                               __nv_bfloat16* __restrict__ tl, int K, int N)
{
    int idx = blockIdx.x * blockDim.x + threadIdx.x;
    if (idx >= K * N) return;
    int k = idx / N, n = idx % N;
    float v = W[idx];
    __nv_bfloat16 hb = __float2bfloat16_rn(v);
    __nv_bfloat16 lb = __float2bfloat16_rn(v - __bfloat162float(hb));
    th[(size_t)n * K + k] = hb;
    tl[(size_t)n * K + k] = lb;
}

// ---------------- mma.sync GEMM: C[M,N] = (Ah+Al)[M,K] @ (Bh+Bl)^T[N,K] -------
// CTA 128x128, K-chunk 32, double-buffered cp.async. 8 warps, warp tile 64x32.
// __launch_bounds__(256, 2): cap regs at 128 so 2 CTAs/SM fit the register file
// (R9 profile: regs=150 -> 1 CTA/SM -> tensor pipe stuck at 52%).
// B-fragments loaded inside the j-loop to keep the live set ~110 regs.
#define TSTRIDE 80
#define TILE_B  (128 * TSTRIDE)          // 10240 B per tile
#define BUF_B   (4 * TILE_B)             // 40960 B per buffer
#define GEMM_SMEM (2 * BUF_B)            // 81920 B

template <int WITH_BIAS>
__global__ void __launch_bounds__(256, 2)
mma_gemm(const __nv_bfloat16* __restrict__ Ah, const __nv_bfloat16* __restrict__ Al,
         const __nv_bfloat16* __restrict__ Bh, const __nv_bfloat16* __restrict__ Bl,
         const float* __restrict__ bias, float* __restrict__ C, int M, int N, int K)
{
    extern __shared__ char smem[];
    const uint32_t sb = smem_u32(smem);
    const int tid = threadIdx.x;
    const int wid = tid >> 5;
    const int lane = tid & 31;
    const int m0 = blockIdx.y * 128;
    const int n0 = blockIdx.x * 128;
    const int wm0 = (wid & 1) * 64;      // warp M offset within CTA tile
    const int wn0 = (wid >> 1) * 32;     // warp N offset

    float acc[4][4][4];
#pragma unroll
    for (int i = 0; i < 4; i++)
#pragma unroll
        for (int j = 0; j < 4; j++)
#pragma unroll
            for (int q = 0; q < 4; q++) acc[i][j][q] = 0.0f;

    const int NC = K / 32;

    auto load_chunk = [&](int c, int buf) {
        const int k0 = c * 32;
        const uint32_t bo = sb + buf * BUF_B;
#pragma unroll
        for (int t = 0; t < 2; t++) {
            int s = tid + t * 256;           // 0..511
            int row = s >> 2, c16 = s & 3;   // 128 rows x 4 16B segs
            uint32_t d = bo + row * TSTRIDE + c16 * 16;
            const __nv_bfloat16* sa = Ah + (size_t)(m0 + row) * K + k0 + c16 * 8;
            CP16(d, sa);
            const __nv_bfloat16* sal = Al + (size_t)(m0 + row) * K + k0 + c16 * 8;
            CP16(d + TILE_B, sal);
            const __nv_bfloat16* sbh = Bh + (size_t)(n0 + row) * K + k0 + c16 * 8;
            CP16(d + 2 * TILE_B, sbh);
            const __nv_bfloat16* sbl = Bl + (size_t)(n0 + row) * K + k0 + c16 * 8;
            CP16(d + 3 * TILE_B, sbl);
        }
        CP_COMMIT();
    };

    load_chunk(0, 0);

    for (int c = 0; c < NC; c++) {
        CP_WAIT0();
        __syncthreads();                 // chunk c visible to all warps
        if (c + 1 < NC) load_chunk(c + 1, (c + 1) & 1);

        const uint32_t bo = sb + (c & 1) * BUF_B;
        const int l4 = lane & 15;
#pragma unroll
        for (int ks = 0; ks < 2; ks++) {
            uint32_t ah[4][4], al[4][4];
            const uint32_t colA = ks * 32 + (lane >> 4) * 16;
            const uint32_t colB = ks * 32 + (l4 >> 3) * 16;
#pragma unroll
            for (int i = 0; i < 4; i++) {
                uint32_t a = bo + (uint32_t)(wm0 + i * 16 + l4) * TSTRIDE + colA;
                ldsm4(ah[i], a);
                ldsm4(al[i], a + TILE_B);
            }
#pragma unroll
            for (int j = 0; j < 4; j++) {
                uint32_t bh2[2], bl2[2];
                uint32_t a = bo + 2 * TILE_B + (uint32_t)(wn0 + j * 8 + (l4 & 7)) * TSTRIDE + colB;
                ldsm2(bh2, a);
                ldsm2(bl2, a + TILE_B);
#pragma unroll
                for (int i = 0; i < 4; i++) {
                    mma_bf16(acc[i][j], ah[i], bh2);
                    mma_bf16(acc[i][j], ah[i], bl2);
                    mma_bf16(acc[i][j], al[i], bh2);
                }
            }
        }
        __syncthreads();                 // buffer c&1 free for chunk c+2
    }

    // ---- epilogue: direct stores (float2 per fragment half) ----
#pragma unroll
    for (int i = 0; i < 4; i++) {
#pragma unroll
        for (int j = 0; j < 4; j++) {
            int m = m0 + wm0 + i * 16 + (lane >> 2);
            int n = n0 + wn0 + j * 8 + (lane & 3) * 2;
            float2 v0 = make_float2(acc[i][j][0], acc[i][j][1]);
            float2 v1 = make_float2(acc[i][j][2], acc[i][j][3]);
            if (WITH_BIAS) {
                float2 bv = *(const float2*)(bias + n);
                v0.x += bv.x; v0.y += bv.y;
                v1.x += bv.x; v1.y += bv.y;
            }
            *(float2*)(C + (size_t)m * N + n) = v0;
            *(float2*)(C + (size_t)(m + 8) * N + n) = v1;
        }
    }
}

// ---------------- Fused causal attention, templated on query block ----------------
// QB in 0..3; kv_len = (QB+1)*64. Writes bf16 hi/lo att directly.
// Smem trims vs R9: QS 65->64 (Q reads are warp-broadcast; padding useless),
// SMS KVLEN+1->KVLEN (P reads broadcast per row-group). QB1 now fits 2 CTAs/SM,
// QB0 fits 3.
template <int QB>
__global__ void __launch_bounds__(256)
attn_kernel(const float* __restrict__ qkv, __nv_bfloat16* __restrict__ ath,
            __nv_bfloat16* __restrict__ atl)
{
    constexpr int KVLEN = (QB + 1) * 64;
    constexpr int JMAX = QB + 1;
    constexpr int QS = 64, KS = 65, VS = 64, SMS = KVLEN;

    extern __shared__ float sm[];
    float* Qs = sm;                    // 64 x 64
    float* Ks = Qs + 64 * QS;          // KVLEN x 65
    float* Vs = Ks + KVLEN * KS;       // KVLEN x 64
    float* Sm = Vs + KVLEN * VS;       // 64 x SMS

    const int tid = threadIdx.x;
    const int blk = blockIdx.x;
    const int hh = blk % NH;
    const int b = blk / NH;
    const float* qkvb = qkv + (size_t)b * SEQ * C3;

    // ---- stage Q (64x64) ----
#pragma unroll
    for (int p = 0; p < 4; p++) {
        int idx = tid + p * 256;
        int r = idx >> 4, f4 = idx & 15;
        float4 v = *(const float4*)(qkvb + (size_t)(QB * 64 + r) * C3 + hh * HD + f4 * 4);
        *(float4*)(Qs + r * QS + f4 * 4) = v;
    }
    // ---- stage K (KVLEN x 64) ----
#pragma unroll
    for (int p = 0; p < JMAX * 4; p++) {
        int idx = tid + p * 256;
        int r = idx >> 4, f4 = idx & 15;
        float4 v = *(const float4*)(qkvb + (size_t)r * C3 + CDIM + hh * HD + f4 * 4);
        float* dst = Ks + r * KS + f4 * 4;
        dst[0] = v.x; dst[1] = v.y; dst[2] = v.z; dst[3] = v.w;
    }
    // ---- stage V (KVLEN x 64) ----
#pragma unroll
    for (int p = 0; p < JMAX * 4; p++) {
        int idx = tid + p * 256;
        int r = idx >> 4, f4 = idx & 15;
        float4 v = *(const float4*)(qkvb + (size_t)r * C3 + 2 * CDIM + hh * HD + f4 * 4);
        *(float4*)(Vs + r * VS + f4 * 4) = v;
    }
    __syncthreads();

    // ---- S = Q @ K^T, rows per warp, strided cols per lane ----
    const int ty = tid >> 5;
    const int tx = tid & 31;

    u64 acc[8][JMAX];
#pragma unroll
    for (int i = 0; i < 8; i++)
#pragma unroll
        for (int j = 0; j < JMAX; j++) acc[i][j] = 0ULL;

#pragma unroll 8
    for (int kk = 0; kk < HD; kk++) {
        float a[8];
        u64 bp[JMAX];
#pragma unroll
        for (int i = 0; i < 8; i++) a[i] = Qs[(ty * 8 + i) * QS + kk];
#pragma unroll
        for (int j = 0; j < JMAX; j++)
            bp[j] = pk2(Ks[(tx + 64 * j) * KS + kk], Ks[(tx + 64 * j + 32) * KS + kk]);
#pragma unroll
        for (int i = 0; i < 8; i++) {
            u64 ap = pk2(a[i], a[i]);
#pragma unroll
            for (int j = 0; j < JMAX; j++) fma2(acc[i][j], ap, bp[j]);
        }
    }

    // ---- causal mask + softmax (registers + shuffles) ----
#pragma unroll
    for (int i = 0; i < 8; i++) {
        const int rg = QB * 64 + ty * 8 + i;
        float s[2 * JMAX];
#pragma unroll
        for (int j = 0; j < JMAX; j++) {
            float2 v = upk(acc[i][j]);
            s[2 * j] = (tx + 64 * j > rg) ? -1e30f : v.x;
            s[2 * j + 1] = (tx + 64 * j + 32 > rg) ? -1e30f : v.y;
        }
        float m = -1e30f;
#pragma unroll
        for (int j = 0; j < 2 * JMAX; j++) m = fmaxf(m, s[j]);
#pragma unroll
        for (int o = 16; o > 0; o >>= 1) m = fmaxf(m, __shfl_xor_sync(0xffffffffu, m, o));

        float p[2 * JMAX];
        float sum = 0.0f;
#pragma unroll
        for (int j = 0; j < 2 * JMAX; j++) {
            float e = (s[j] <= -1e29f) ? 0.0f : __expf(s[j] - m);
            p[j] = e; sum += e;
        }
#pragma unroll
        for (int o = 16; o > 0; o >>= 1) sum += __shfl_xor_sync(0xffffffffu, sum, o);
        float inv = 1.0f / sum;

        float* row = Sm + (ty * 8 + i) * SMS;
#pragma unroll
        for (int j = 0; j < JMAX; j++) {
            row[tx + 64 * j] = p[2 * j] * inv;
            row[tx + 64 * j + 32] = p[2 * j + 1] * inv;
        }
    }
    __syncthreads();

    // ---- O = P @ V ----
    const int ty2 = tid >> 4;   // rows ty2*4..+3
    const int tx2 = tid & 15;   // cols tx2*4..+3

    u64 oacc[4][2];
#pragma unroll
    for (int i = 0; i < 4; i++) { oacc[i][0] = 0ULL; oacc[i][1] = 0ULL; }

#pragma unroll 4
    for (int kk = 0; kk < KVLEN; kk++) {
        float4 bv = *(const float4*)(Vs + kk * VS + tx2 * 4);
        u64 bp0 = pk2(bv.x, bv.y);
        u64 bp1 = pk2(bv.z, bv.w);
#pragma unroll
        for (int i = 0; i < 4; i++) {
            float av = Sm[(ty2 * 4 + i) * SMS + kk];
            u64 ap = pk2(av, av);
            fma2(oacc[i][0], ap, bp0);
            fma2(oacc[i][1], ap, bp1);
        }
    }

#pragma unroll
    for (int i = 0; i < 4; i++) {
        int t = QB * 64 + ty2 * 4 + i;
        float2 x0 = upk(oacc[i][0]);
        float2 x1 = upk(oacc[i][1]);
        float o[4] = {x0.x, x0.y, x1.x, x1.y};
        size_t base = ((size_t)(b * SEQ + t)) * CDIM + hh * HD + tx2 * 4;
        __nv_bfloat16 hv[4], lv[4];
#pragma unroll
        for (int q = 0; q < 4; q++) {
            hv[q] = __float2bfloat16_rn(o[q]);
            lv[q] = __float2bfloat16_rn(o[q] - __bfloat162float(hv[q]));
        }
        __nv_bfloat162 t0, t1;
        t0.x = hv[0]; t0.y = hv[1]; t1.x = hv[2]; t1.y = hv[3];
        ((__nv_bfloat162*)(ath + base))[0] = t0;
        ((__nv_bfloat162*)(ath + base))[1] = t1;
        t0.x = lv[0]; t0.y = lv[1]; t1.x = lv[2]; t1.y = lv[3];
        ((__nv_bfloat162*)(atl + base))[0] = t0;
        ((__nv_bfloat162*)(atl + base))[1] = t1;
    }
}

// smem bytes per QB
template <int QB> struct AttnSmem {
    static constexpr int KVLEN = (QB + 1) * 64;
    static constexpr int BYTES = (64 * 64 + KVLEN * 65 + KVLEN * 64 + 64 * KVLEN) * 4;
};

// ---------------- launch ----------------
extern "C" void kernel_launch(void* const* d_in, const int* in_sizes, int n_in,
                              void* d_out, int out_size)
{
    const float* x     = (const float*)d_in[0];
    const float* Wqkv  = (const float*)d_in[1];
    const float* Wproj = (const float*)d_in[2];
    const float* bproj = (const float*)d_in[3];
    float* out = (float*)d_out;

    float *qkvp = nullptr;
    __nv_bfloat16 *xh, *xl, *ath, *atl, *wqh, *wql, *wph, *wpl;
    cudaGetSymbolAddress((void**)&qkvp, mha_qkv);
    cudaGetSymbolAddress((void**)&xh, mha_xh);
    cudaGetSymbolAddress((void**)&xl, mha_xl);
    cudaGetSymbolAddress((void**)&ath, mha_ath);
    cudaGetSymbolAddress((void**)&atl, mha_atl);
    cudaGetSymbolAddress((void**)&wqh, mha_wqh);
    cudaGetSymbolAddress((void**)&wql, mha_wql);
    cudaGetSymbolAddress((void**)&wph, mha_wph);
    cudaGetSymbolAddress((void**)&wpl, mha_wpl);

    cudaFuncSetAttribute(mma_gemm<0>, cudaFuncAttributeMaxDynamicSharedMemorySize, GEMM_SMEM);
    cudaFuncSetAttribute(mma_gemm<1>, cudaFuncAttributeMaxDynamicSharedMemorySize, GEMM_SMEM);
    cudaFuncSetAttribute(attn_kernel<0>, cudaFuncAttributeMaxDynamicSharedMemorySize, AttnSmem<0>::BYTES);
    cudaFuncSetAttribute(attn_kernel<1>, cudaFuncAttributeMaxDynamicSharedMemorySize, AttnSmem<1>::BYTES);
    cudaFuncSetAttribute(attn_kernel<2>, cudaFuncAttributeMaxDynamicSharedMemorySize, AttnSmem<2>::BYTES);
    cudaFuncSetAttribute(attn_kernel<3>, cudaFuncAttributeMaxDynamicSharedMemorySize, AttnSmem<3>::BYTES);

    // 0) bf16 hi/lo splits
    {
        int n4 = MTOT * CDIM / 4;
        split_kernel<<<(n4 + 255) / 256, 256>>>(x, xh, xl, n4);
        int nw1 = CDIM * C3;
        split_t_kernel<<<(nw1 + 255) / 256, 256>>>(Wqkv, wqh, wql, CDIM, C3);
        int nw2 = CDIM * CDIM;
        split_t_kernel<<<(nw2 + 255) / 256, 256>>>(Wproj, wph, wpl, CDIM, CDIM);
    }

    // 1) qkv = x @ Wqkv  (mma.sync bf16x3, M=65536, N=1152, K=384)
    mma_gemm<0><<<dim3(C3 / 128, MTOT / 128), 256, GEMM_SMEM>>>(xh, xl, wqh, wql, nullptr,
                                                                qkvp, MTOT, C3, CDIM);

    // 2) fused causal attention (per query block template)
    attn_kernel<0><<<BATCH * NH, 256, AttnSmem<0>::BYTES>>>(qkvp, ath, atl);
    attn_kernel<1><<<BATCH * NH, 256, AttnSmem<1>::BYTES>>>(qkvp, ath, atl);
    attn_kernel<2><<<BATCH * NH, 256, AttnSmem<2>::BYTES>>>(qkvp, ath, atl);
    attn_kernel<3><<<BATCH * NH, 256, AttnSmem<3>::BYTES>>>(qkvp, ath, atl);

    // 3) out = att @ Wproj + bias  (mma.sync bf16x3, N=384, K=384)
    mma_gemm<1><<<dim3(CDIM / 128, MTOT / 128), 256, GEMM_SMEM>>>(ath, atl, wph, wpl, bproj,
                                                                  out, MTOT, CDIM, CDIM);
}